// round 1
// baseline (speedup 1.0000x reference)
#include <cuda_runtime.h>
#include <cuda_bf16.h>

// Problem constants (fixed shapes per reference)
#define E_TOTAL   3200000
#define NN        100000
#define EDGE_DIM  64
#define ADDED     24
#define H_DIM     256
#define KDIM      280
#define OUT_DIM   256

// Scatter-sum scratch: [NN, ADDED] fp32 = 9.6 MB (fits in L2 for atomics)
__device__ float g_ah[NN * ADDED];

// ---------------- packed f32x2 helpers ----------------
__device__ __forceinline__ unsigned long long pack2(float lo, float hi) {
    unsigned long long r;
    asm("mov.b64 %0, {%1, %2};" : "=l"(r) : "f"(lo), "f"(hi));
    return r;
}
__device__ __forceinline__ void unpack2(unsigned long long v, float& lo, float& hi) {
    asm("mov.b64 {%0, %1}, %2;" : "=f"(lo), "=f"(hi) : "l"(v));
}
// Packed dual fp32 FMA (sm_103a): d = a*b + c on both 32-bit halves.
__device__ __forceinline__ unsigned long long ffma2(unsigned long long a,
                                                    unsigned long long b,
                                                    unsigned long long c) {
    unsigned long long d;
    asm("fma.rn.f32x2 %0, %1, %2, %3;" : "=l"(d) : "l"(a), "l"(b), "l"(c));
    return d;
}

// ---------------- kernel 0: zero the scatter buffer ----------------
__global__ void zero_ah_kernel() {
    int i = blockIdx.x * blockDim.x + threadIdx.x;
    const int n4 = NN * ADDED / 4;  // 600000
    if (i < n4) {
        reinterpret_cast<float4*>(g_ah)[i] = make_float4(0.f, 0.f, 0.f, 0.f);
    }
}

// ---------------- kernel 1: edge projection + scatter-add ----------------
// Each thread handles 2 edges (e, e + E/2) so every LDS of W serves 2 FFMA2s.
// m_e = edge_feat[e] @ W_msg + b_msg ; atomicAdd into g_ah[dst[e]].
__global__ __launch_bounds__(256) void edge_kernel(
    const float* __restrict__ edge_feat,   // [E, 64]
    const float* __restrict__ W_msg,       // [64, 24]
    const float* __restrict__ b_msg,       // [24]
    const int*   __restrict__ dst_idx)     // [E]
{
    __shared__ unsigned long long Wp[EDGE_DIM][ADDED / 2];  // 64 x 12 packed pairs
    __shared__ unsigned long long bp[ADDED / 2];

    const int tid = threadIdx.x;
    for (int idx = tid; idx < EDGE_DIM * (ADDED / 2); idx += blockDim.x) {
        int k = idx / (ADDED / 2);
        int j = idx % (ADDED / 2);
        Wp[k][j] = pack2(W_msg[k * ADDED + 2 * j], W_msg[k * ADDED + 2 * j + 1]);
    }
    if (tid < ADDED / 2) bp[tid] = pack2(b_msg[2 * tid], b_msg[2 * tid + 1]);
    __syncthreads();

    const long long gid = (long long)blockIdx.x * blockDim.x + tid;
    const long long e0 = gid;
    const long long e1 = gid + (E_TOTAL / 2);
    if (e0 >= E_TOTAL / 2) return;

    const float4* f0 = reinterpret_cast<const float4*>(edge_feat) + e0 * (EDGE_DIM / 4);
    const float4* f1 = reinterpret_cast<const float4*>(edge_feat) + e1 * (EDGE_DIM / 4);

    unsigned long long acc0[ADDED / 2], acc1[ADDED / 2];
#pragma unroll
    for (int j = 0; j < ADDED / 2; j++) { acc0[j] = bp[j]; acc1[j] = bp[j]; }

#pragma unroll
    for (int k4 = 0; k4 < EDGE_DIM / 4; k4++) {
        float4 va = f0[k4];
        float4 vb = f1[k4];
        float ea[4] = {va.x, va.y, va.z, va.w};
        float eb[4] = {vb.x, vb.y, vb.z, vb.w};
#pragma unroll
        for (int s = 0; s < 4; s++) {
            int k = k4 * 4 + s;
            unsigned long long pa = pack2(ea[s], ea[s]);
            unsigned long long pb = pack2(eb[s], eb[s]);
#pragma unroll
            for (int j = 0; j < ADDED / 2; j++) {
                unsigned long long w = Wp[k][j];
                acc0[j] = ffma2(pa, w, acc0[j]);
                acc1[j] = ffma2(pb, w, acc1[j]);
            }
        }
    }

    const int d0 = dst_idx[e0];
    const int d1 = dst_idx[e1];
    float* p0 = g_ah + (long long)d0 * ADDED;
    float* p1 = g_ah + (long long)d1 * ADDED;
#pragma unroll
    for (int j = 0; j < ADDED / 2; j++) {
        float x0, x1;
        unpack2(acc0[j], x0, x1);
        atomicAdd(p0 + 2 * j, x0);
        atomicAdd(p0 + 2 * j + 1, x1);
    }
#pragma unroll
    for (int j = 0; j < ADDED / 2; j++) {
        float y0, y1;
        unpack2(acc1[j], y0, y1);
        atomicAdd(p1 + 2 * j, y0);
        atomicAdd(p1 + 2 * j + 1, y1);
    }
}

// ---------------- kernel 2: node GEMM + bias + ReLU ----------------
// out[n] = relu(concat(h[n], g_ah[n]*norm[n]) @ W1 + b1)
// Block tile: 64 rows x 256 cols, 256 threads (16x16).
// Thread (tx,ty): rows ty*4..+3, cols {32*c + 2*tx : c in 0..7} (swizzled for
// conflict-free LDS.64 of W tile: for fixed c, lanes tx=0..15 cover all 32 banks).
__global__ __launch_bounds__(256, 2) void node_kernel(
    const float* __restrict__ h,      // [NN, 256]
    const float* __restrict__ norm,   // [NN, 1]
    const float* __restrict__ W1,     // [280, 256]
    const float* __restrict__ b1,     // [256]
    float* __restrict__ out)          // [NN, 256]
{
    __shared__ __align__(16) float xs[64][10];   // 64 rows x 8 k (pad 10)
    __shared__ __align__(16) float ws[8][256];   // 8 k x 256 cols

    const int tid = threadIdx.x;
    const int tx = tid & 15;   // col group
    const int ty = tid >> 4;   // row group
    const int row0 = blockIdx.x * 64;

    unsigned long long acc[4][8];
#pragma unroll
    for (int i = 0; i < 4; i++)
#pragma unroll
        for (int c = 0; c < 8; c++) acc[i][c] = 0ULL;

    // x-tile loader assignment: thread -> (row r, k-pair kk)
    const int lr = tid >> 2;          // 0..63
    const int lk = (tid & 3) * 2;     // 0,2,4,6

    for (int kt = 0; kt < KDIM / 8; kt++) {   // 35 tiles
        const int kbase = kt * 8;

        // load W tile: rows kbase..kbase+7, full 256 width = 2048 contiguous floats
        {
            const float4* wsrc = reinterpret_cast<const float4*>(W1 + kbase * OUT_DIM);
            float4* wdst = reinterpret_cast<float4*>(&ws[0][0]);
            wdst[tid] = wsrc[tid];
            wdst[tid + 256] = wsrc[tid + 256];
        }
        // load x tile (64 rows x 8 k), one float2 per thread
        {
            const int row = row0 + lr;
            const int k0 = kbase + lk;   // pair (k0, k0+1); never straddles 256
            float2 v = make_float2(0.f, 0.f);
            if (row < NN) {
                if (k0 < H_DIM) {
                    v = *reinterpret_cast<const float2*>(h + (long long)row * H_DIM + k0);
                } else {
                    float nr = norm[row];
                    v.x = g_ah[row * ADDED + (k0 - H_DIM)] * nr;
                    v.y = g_ah[row * ADDED + (k0 - H_DIM) + 1] * nr;
                }
            }
            xs[lr][lk] = v.x;
            xs[lr][lk + 1] = v.y;
        }
        __syncthreads();

#pragma unroll
        for (int k = 0; k < 8; k++) {
            unsigned long long a[4];
#pragma unroll
            for (int i = 0; i < 4; i++) {
                float av = xs[ty * 4 + i][k];
                a[i] = pack2(av, av);
            }
#pragma unroll
            for (int c = 0; c < 8; c++) {
                unsigned long long w =
                    *reinterpret_cast<const unsigned long long*>(&ws[k][32 * c + 2 * tx]);
#pragma unroll
                for (int i = 0; i < 4; i++) acc[i][c] = ffma2(a[i], w, acc[i][c]);
            }
        }
        __syncthreads();
    }

    // epilogue: + b1, ReLU, store
#pragma unroll
    for (int c = 0; c < 8; c++) {
        const int col = 32 * c + 2 * tx;
        const float bb0 = b1[col];
        const float bb1 = b1[col + 1];
#pragma unroll
        for (int i = 0; i < 4; i++) {
            const int row = row0 + ty * 4 + i;
            if (row < NN) {
                float x0, x1;
                unpack2(acc[i][c], x0, x1);
                x0 = fmaxf(x0 + bb0, 0.f);
                x1 = fmaxf(x1 + bb1, 0.f);
                *reinterpret_cast<float2*>(out + (long long)row * OUT_DIM + col) =
                    make_float2(x0, x1);
            }
        }
    }
}

// ---------------- launch ----------------
extern "C" void kernel_launch(void* const* d_in, const int* in_sizes, int n_in,
                              void* d_out, int out_size) {
    const float* h         = (const float*)d_in[0];
    const float* edge_feat = (const float*)d_in[1];
    const float* norm      = (const float*)d_in[2];
    const float* W_msg     = (const float*)d_in[3];
    const float* b_msg     = (const float*)d_in[4];
    const float* W1        = (const float*)d_in[5];
    const float* b1        = (const float*)d_in[6];
    const int*   dst_idx   = (const int*)d_in[7];
    float* out = (float*)d_out;

    // 1. zero scatter buffer (600000 float4)
    zero_ah_kernel<<<(NN * ADDED / 4 + 255) / 256, 256>>>();

    // 2. edge projection + scatter  (1.6M threads, 2 edges each)
    edge_kernel<<<(E_TOTAL / 2) / 256, 256>>>(edge_feat, W_msg, b_msg, dst_idx);

    // 3. node GEMM + bias + ReLU
    node_kernel<<<(NN + 63) / 64, 256>>>(h, norm, W1, b1, out);
}

// round 2
// speedup vs baseline: 1.2565x; 1.2565x over previous
#include <cuda_runtime.h>
#include <cuda_bf16.h>

// Problem constants (fixed shapes per reference)
#define E_TOTAL   3200000
#define NN        100000
#define EDGE_DIM  64
#define ADDED     24
#define H_DIM     256
#define KDIM      280
#define OUT_DIM   256

// Scatter-sum scratch: [NN, ADDED] fp32 = 9.6 MB.
// Zero-initialized at module load; node_kernel re-zeroes its rows after
// consuming them, so the zero invariant holds across graph replays.
__device__ float g_ah[NN * ADDED];

// ---------------- packed f32x2 helpers ----------------
__device__ __forceinline__ unsigned long long pack2(float lo, float hi) {
    unsigned long long r;
    asm("mov.b64 %0, {%1, %2};" : "=l"(r) : "f"(lo), "f"(hi));
    return r;
}
__device__ __forceinline__ void unpack2(unsigned long long v, float& lo, float& hi) {
    asm("mov.b64 {%0, %1}, %2;" : "=f"(lo), "=f"(hi) : "l"(v));
}
// Packed dual fp32 FMA (sm_103a FFMA2): d = a*b + c on both 32-bit halves.
__device__ __forceinline__ unsigned long long ffma2(unsigned long long a,
                                                    unsigned long long b,
                                                    unsigned long long c) {
    unsigned long long d;
    asm("fma.rn.f32x2 %0, %1, %2, %3;" : "=l"(d) : "l"(a), "l"(b), "l"(c));
    return d;
}
// Vectorized global float reduction (sm_90+): one REDG for 4 floats.
__device__ __forceinline__ void red_add_v4(float* p, float a, float b, float c, float d) {
    asm volatile("red.global.add.v4.f32 [%0], {%1, %2, %3, %4};"
                 :: "l"(p), "f"(a), "f"(b), "f"(c), "f"(d) : "memory");
}

// ---------------- kernel 1: edge projection + scatter-add ----------------
// Each thread handles 2 edges (e, e + E/2) so every LDS of W serves 2 FFMA2s.
// m_e = edge_feat[e] @ W_msg + b_msg ; red.v4 into g_ah[dst[e]].
__global__ __launch_bounds__(256) void edge_kernel(
    const float* __restrict__ edge_feat,   // [E, 64]
    const float* __restrict__ W_msg,       // [64, 24]
    const float* __restrict__ b_msg,       // [24]
    const int*   __restrict__ dst_idx)     // [E]
{
    __shared__ unsigned long long Wp[EDGE_DIM][ADDED / 2];  // 64 x 12 packed pairs
    __shared__ unsigned long long bp[ADDED / 2];

    const int tid = threadIdx.x;
    for (int idx = tid; idx < EDGE_DIM * (ADDED / 2); idx += blockDim.x) {
        int k = idx / (ADDED / 2);
        int j = idx % (ADDED / 2);
        Wp[k][j] = pack2(W_msg[k * ADDED + 2 * j], W_msg[k * ADDED + 2 * j + 1]);
    }
    if (tid < ADDED / 2) bp[tid] = pack2(b_msg[2 * tid], b_msg[2 * tid + 1]);
    __syncthreads();

    const long long gid = (long long)blockIdx.x * blockDim.x + tid;
    const long long e0 = gid;
    const long long e1 = gid + (E_TOTAL / 2);
    if (e0 >= E_TOTAL / 2) return;

    const float4* f0 = reinterpret_cast<const float4*>(edge_feat) + e0 * (EDGE_DIM / 4);
    const float4* f1 = reinterpret_cast<const float4*>(edge_feat) + e1 * (EDGE_DIM / 4);

    unsigned long long acc0[ADDED / 2], acc1[ADDED / 2];
#pragma unroll
    for (int j = 0; j < ADDED / 2; j++) { acc0[j] = bp[j]; acc1[j] = bp[j]; }

#pragma unroll
    for (int k4 = 0; k4 < EDGE_DIM / 4; k4++) {
        float4 va = f0[k4];
        float4 vb = f1[k4];
        float ea[4] = {va.x, va.y, va.z, va.w};
        float eb[4] = {vb.x, vb.y, vb.z, vb.w};
#pragma unroll
        for (int s = 0; s < 4; s++) {
            int k = k4 * 4 + s;
            unsigned long long pa = pack2(ea[s], ea[s]);
            unsigned long long pb = pack2(eb[s], eb[s]);
#pragma unroll
            for (int j = 0; j < ADDED / 2; j++) {
                unsigned long long w = Wp[k][j];
                acc0[j] = ffma2(pa, w, acc0[j]);
                acc1[j] = ffma2(pb, w, acc1[j]);
            }
        }
    }

    const int d0 = dst_idx[e0];
    const int d1 = dst_idx[e1];
    float* p0 = g_ah + (long long)d0 * ADDED;   // rows are 96B -> 16B aligned
    float* p1 = g_ah + (long long)d1 * ADDED;
#pragma unroll
    for (int q = 0; q < ADDED / 4; q++) {       // 6 v4 reductions per edge
        float x0, x1, x2, x3;
        unpack2(acc0[2 * q],     x0, x1);
        unpack2(acc0[2 * q + 1], x2, x3);
        red_add_v4(p0 + 4 * q, x0, x1, x2, x3);
    }
#pragma unroll
    for (int q = 0; q < ADDED / 4; q++) {
        float y0, y1, y2, y3;
        unpack2(acc1[2 * q],     y0, y1);
        unpack2(acc1[2 * q + 1], y2, y3);
        red_add_v4(p1 + 4 * q, y0, y1, y2, y3);
    }
}

// ---------------- kernel 2: node GEMM + bias + ReLU + g_ah re-zero ----------
// out[n] = relu(concat(h[n], g_ah[n]*norm[n]) @ W1 + b1)
// Block tile: 64 rows x 256 cols, 256 threads (16x16).
__global__ __launch_bounds__(256, 2) void node_kernel(
    const float* __restrict__ h,      // [NN, 256]
    const float* __restrict__ norm,   // [NN, 1]
    const float* __restrict__ W1,     // [280, 256]
    const float* __restrict__ b1,     // [256]
    float* __restrict__ out)          // [NN, 256]
{
    __shared__ __align__(16) float xs[64][10];   // 64 rows x 8 k (pad 10)
    __shared__ __align__(16) float ws[8][256];   // 8 k x 256 cols

    const int tid = threadIdx.x;
    const int tx = tid & 15;   // col group
    const int ty = tid >> 4;   // row group
    const int row0 = blockIdx.x * 64;

    unsigned long long acc[4][8];
#pragma unroll
    for (int i = 0; i < 4; i++)
#pragma unroll
        for (int c = 0; c < 8; c++) acc[i][c] = 0ULL;

    // x-tile loader assignment: thread -> (row r, k-pair kk)
    const int lr = tid >> 2;          // 0..63
    const int lk = (tid & 3) * 2;     // 0,2,4,6

    for (int kt = 0; kt < KDIM / 8; kt++) {   // 35 tiles
        const int kbase = kt * 8;

        // load W tile: rows kbase..kbase+7, full 256 width = 2048 contiguous floats
        {
            const float4* wsrc = reinterpret_cast<const float4*>(W1 + kbase * OUT_DIM);
            float4* wdst = reinterpret_cast<float4*>(&ws[0][0]);
            wdst[tid] = wsrc[tid];
            wdst[tid + 256] = wsrc[tid + 256];
        }
        // load x tile (64 rows x 8 k), one float2 per thread
        {
            const int row = row0 + lr;
            const int k0 = kbase + lk;   // pair (k0, k0+1); never straddles 256
            float2 v = make_float2(0.f, 0.f);
            if (row < NN) {
                if (k0 < H_DIM) {
                    v = *reinterpret_cast<const float2*>(h + (long long)row * H_DIM + k0);
                } else {
                    float nr = norm[row];
                    v.x = g_ah[row * ADDED + (k0 - H_DIM)] * nr;
                    v.y = g_ah[row * ADDED + (k0 - H_DIM) + 1] * nr;
                }
            }
            xs[lr][lk] = v.x;
            xs[lr][lk + 1] = v.y;
        }
        __syncthreads();

#pragma unroll
        for (int k = 0; k < 8; k++) {
            unsigned long long a[4];
#pragma unroll
            for (int i = 0; i < 4; i++) {
                float av = xs[ty * 4 + i][k];
                a[i] = pack2(av, av);
            }
#pragma unroll
            for (int c = 0; c < 8; c++) {
                unsigned long long w =
                    *reinterpret_cast<const unsigned long long*>(&ws[k][32 * c + 2 * tx]);
#pragma unroll
                for (int i = 0; i < 4; i++) acc[i][c] = ffma2(a[i], w, acc[i][c]);
            }
        }
        __syncthreads();
    }

    // Re-zero this block's g_ah rows for the next graph replay.
    // All reads of g_ah by this block completed before the last __syncthreads.
    {
        const int base4 = row0 * (ADDED / 4);          // float4 index of block start
        const int total4 = NN * (ADDED / 4);           // 600000
        for (int i = tid; i < 64 * (ADDED / 4); i += 256) {
            if (base4 + i < total4)
                reinterpret_cast<float4*>(g_ah)[base4 + i] = make_float4(0.f, 0.f, 0.f, 0.f);
        }
    }

    // epilogue: + b1, ReLU, store
#pragma unroll
    for (int c = 0; c < 8; c++) {
        const int col = 32 * c + 2 * tx;
        const float bb0 = b1[col];
        const float bb1 = b1[col + 1];
#pragma unroll
        for (int i = 0; i < 4; i++) {
            const int row = row0 + ty * 4 + i;
            if (row < NN) {
                float x0, x1;
                unpack2(acc[i][c], x0, x1);
                x0 = fmaxf(x0 + bb0, 0.f);
                x1 = fmaxf(x1 + bb1, 0.f);
                *reinterpret_cast<float2*>(out + (long long)row * OUT_DIM + col) =
                    make_float2(x0, x1);
            }
        }
    }
}

// ---------------- launch ----------------
extern "C" void kernel_launch(void* const* d_in, const int* in_sizes, int n_in,
                              void* d_out, int out_size) {
    const float* h         = (const float*)d_in[0];
    const float* edge_feat = (const float*)d_in[1];
    const float* norm      = (const float*)d_in[2];
    const float* W_msg     = (const float*)d_in[3];
    const float* b_msg     = (const float*)d_in[4];
    const float* W1        = (const float*)d_in[5];
    const float* b1        = (const float*)d_in[6];
    const int*   dst_idx   = (const int*)d_in[7];
    float* out = (float*)d_out;

    // 1. edge projection + scatter (1.6M threads, 2 edges each)
    edge_kernel<<<(E_TOTAL / 2) / 256, 256>>>(edge_feat, W_msg, b_msg, dst_idx);

    // 2. node GEMM + bias + ReLU (+ re-zero of g_ah for next replay)
    node_kernel<<<(NN + 63) / 64, 256>>>(h, norm, W1, b1, out);
}